// round 2
// baseline (speedup 1.0000x reference)
#include <cuda_runtime.h>
#include <cstdint>

#define NNODES 100000
#define NEDGES 640000
#define CIN    128
#define C2     256

__device__ float g_h[NNODES * CIN];            // (1+eps)*x + scatter-add
__device__ float g_h1[(size_t)NNODES * C2];    // post-LN/ReLU hidden

// ---- tf32 helpers (3xTF32 split) ----
__device__ __forceinline__ uint32_t cvt_tf32(float v) {
    uint32_t r; asm("cvt.rna.tf32.f32 %0, %1;" : "=r"(r) : "f"(v)); return r;
}
__device__ __forceinline__ void split_tf32(float v, uint32_t& hi, uint32_t& lo) {
    hi = cvt_tf32(v);
    lo = cvt_tf32(v - __uint_as_float(hi));
}
__device__ __forceinline__ void mma8(float* d, const uint32_t* a, const uint32_t* b) {
    asm volatile(
        "mma.sync.aligned.m16n8k8.row.col.f32.tf32.tf32.f32 "
        "{%0,%1,%2,%3}, {%4,%5,%6,%7}, {%8,%9}, {%0,%1,%2,%3};\n"
        : "+f"(d[0]), "+f"(d[1]), "+f"(d[2]), "+f"(d[3])
        : "r"(a[0]), "r"(a[1]), "r"(a[2]), "r"(a[3]), "r"(b[0]), "r"(b[1]));
}
__device__ __forceinline__ void red_add_v4(float* p, float a, float b, float c, float d) {
    asm volatile("red.global.add.v4.f32 [%0], {%1,%2,%3,%4};"
                 :: "l"(p), "f"(a), "f"(b), "f"(c), "f"(d) : "memory");
}

// ---- kernel 0: h = (1+eps)*x ----
__global__ __launch_bounds__(256) void k_init(const float* __restrict__ x,
                                              const float* __restrict__ eps) {
    int i = blockIdx.x * 256 + threadIdx.x;
    const int total = NNODES * CIN / 4;
    if (i < total) {
        float s = 1.0f + eps[0];
        float4 v = ((const float4*)x)[i];
        v.x *= s; v.y *= s; v.z *= s; v.w *= s;
        ((float4*)g_h)[i] = v;
    }
}

// ---- kernel 1: msg = relu(x[src] + ea@We + be); scatter-add into g_h[dst] ----
#define E_LDA 68
#define E_LDB 132
#define E_LDM 132
#define E_SB  8704
#define E_SBE 17152
#define E_SIDX 17280
#define E_NF  17536

__global__ __launch_bounds__(256) void k_edge(
    const float* __restrict__ x, const int* __restrict__ ei,
    const float* __restrict__ ea, const float* __restrict__ We,
    const float* __restrict__ be)
{
    extern __shared__ float sm[];
    const int tid = threadIdx.x;
    const int e0 = blockIdx.x * 128;

    #pragma unroll
    for (int it = 0; it < 8; ++it) {                    // A: ea tile [128][64]
        int f = tid + it * 256;
        int e = f >> 4, k4 = (f & 15) << 2;
        *(float4*)&sm[e * E_LDA + k4] = *(const float4*)&ea[(e0 + e) * 64 + k4];
    }
    #pragma unroll
    for (int it = 0; it < 8; ++it) {                    // B: We [64][128]
        int f = tid + it * 256;
        int k = f >> 5, n4 = (f & 31) << 2;
        *(float4*)&sm[E_SB + k * E_LDB + n4] = *(const float4*)&We[k * 128 + n4];
    }
    int* sIdx = (int*)&sm[E_SIDX];
    if (tid < 128) {
        sm[E_SBE + tid] = be[tid];
        sIdx[tid]       = ei[e0 + tid];                 // dst
        sIdx[128 + tid] = ei[NEDGES + e0 + tid];        // src
    }
    __syncthreads();

    const int lane = tid & 31, wid = tid >> 5;
    const int g = lane >> 2, tg = lane & 3;
    const int m0 = (wid >> 2) * 64, n0 = (wid & 3) * 32;

    float acc[4][4][4];
    #pragma unroll
    for (int i = 0; i < 4; ++i)
        #pragma unroll
        for (int j = 0; j < 4; ++j)
            #pragma unroll
            for (int r = 0; r < 4; ++r) acc[i][j][r] = 0.f;

    #pragma unroll
    for (int k0 = 0; k0 < 64; k0 += 8) {
        uint32_t bh[4][2], bl[4][2];
        #pragma unroll
        for (int nt = 0; nt < 4; ++nt) {
            int n = n0 + nt * 8 + g;
            split_tf32(sm[E_SB + (k0 + tg) * E_LDB + n],     bh[nt][0], bl[nt][0]);
            split_tf32(sm[E_SB + (k0 + tg + 4) * E_LDB + n], bh[nt][1], bl[nt][1]);
        }
        #pragma unroll
        for (int mt = 0; mt < 4; ++mt) {
            int mr = m0 + mt * 16;
            uint32_t ah[4], al[4];
            split_tf32(sm[(mr + g) * E_LDA + k0 + tg],         ah[0], al[0]);
            split_tf32(sm[(mr + g + 8) * E_LDA + k0 + tg],     ah[1], al[1]);
            split_tf32(sm[(mr + g) * E_LDA + k0 + tg + 4],     ah[2], al[2]);
            split_tf32(sm[(mr + g + 8) * E_LDA + k0 + tg + 4], ah[3], al[3]);
            #pragma unroll
            for (int nt = 0; nt < 4; ++nt) {
                mma8(acc[mt][nt], ah, bh[nt]);
                mma8(acc[mt][nt], al, bh[nt]);
                mma8(acc[mt][nt], ah, bl[nt]);
            }
        }
    }
    __syncthreads();                                    // done reading A/B

    #pragma unroll
    for (int mt = 0; mt < 4; ++mt)
        #pragma unroll
        for (int nt = 0; nt < 4; ++nt) {                // stage msg [128][132]
            int r = m0 + mt * 16 + g, c = n0 + nt * 8 + tg * 2;
            sm[r * E_LDM + c]           = acc[mt][nt][0];
            sm[r * E_LDM + c + 1]       = acc[mt][nt][1];
            sm[(r + 8) * E_LDM + c]     = acc[mt][nt][2];
            sm[(r + 8) * E_LDM + c + 1] = acc[mt][nt][3];
        }
    __syncthreads();

    #pragma unroll
    for (int p = 0; p < 4; ++p) {                       // gather+relu+scatter
        int r  = p * 32 + (tid >> 3);
        int c0 = (tid & 7) * 16;
        int dst = sIdx[r], src = sIdx[128 + r];
        const float* xp = x + src * CIN;
        float* hp = g_h + dst * CIN;
        #pragma unroll
        for (int q = 0; q < 4; ++q) {
            int c = c0 + q * 4;
            float4 mv = *(float4*)&sm[r * E_LDM + c];
            float4 xv = *(const float4*)&xp[c];
            float4 bv = *(const float4*)&sm[E_SBE + c];
            red_add_v4(hp + c,
                       fmaxf(mv.x + xv.x + bv.x, 0.f),
                       fmaxf(mv.y + xv.y + bv.y, 0.f),
                       fmaxf(mv.z + xv.z + bv.z, 0.f),
                       fmaxf(mv.w + xv.w + bv.w, 0.f));
        }
    }
}

// ---- kernel 2: g_h1 = relu(LN(h@W1 + b1)) ----
#define M1_LDA 136
#define M1_LDB 264
#define M1_LDH 260
#define M1_SB  8704
#define M1_NF  17152

__global__ __launch_bounds__(256) void k_mlp1(
    const float* __restrict__ W1, const float* __restrict__ b1,
    const float* __restrict__ gamma, const float* __restrict__ beta)
{
    extern __shared__ float sm[];
    const int tid = threadIdx.x;
    const int node0 = blockIdx.x * 64;
    const int lane = tid & 31, wid = tid >> 5;
    const int g = lane >> 2, tg = lane & 3;
    const int m0 = (wid >> 2) * 32, n0 = (wid & 3) * 64;

    #pragma unroll
    for (int it = 0; it < 8; ++it) {                    // A: h tile [64][128]
        int f = tid + it * 256;
        int r = f >> 5, k4 = (f & 31) << 2;
        float4 v = make_float4(0.f, 0.f, 0.f, 0.f);
        if (node0 + r < NNODES) v = *(const float4*)&g_h[(node0 + r) * CIN + k4];
        *(float4*)&sm[r * M1_LDA + k4] = v;
    }

    float acc[2][8][4];
    #pragma unroll
    for (int i = 0; i < 2; ++i)
        #pragma unroll
        for (int j = 0; j < 8; ++j)
            #pragma unroll
            for (int r = 0; r < 4; ++r) acc[i][j][r] = 0.f;

    for (int kc = 0; kc < 4; ++kc) {
        __syncthreads();
        #pragma unroll
        for (int it = 0; it < 8; ++it) {                // B chunk: W1[32][256]
            int f = tid + it * 256;
            int k = f >> 6, n4 = (f & 63) << 2;
            *(float4*)&sm[M1_SB + k * M1_LDB + n4] =
                *(const float4*)&W1[(kc * 32 + k) * C2 + n4];
        }
        __syncthreads();
        #pragma unroll
        for (int kk = 0; kk < 32; kk += 8) {
            int ka = kc * 32 + kk;
            #pragma unroll
            for (int mt = 0; mt < 2; ++mt) {
                int mr = m0 + mt * 16;
                uint32_t ah[4], al[4];
                split_tf32(sm[(mr + g) * M1_LDA + ka + tg],         ah[0], al[0]);
                split_tf32(sm[(mr + g + 8) * M1_LDA + ka + tg],     ah[1], al[1]);
                split_tf32(sm[(mr + g) * M1_LDA + ka + tg + 4],     ah[2], al[2]);
                split_tf32(sm[(mr + g + 8) * M1_LDA + ka + tg + 4], ah[3], al[3]);
                #pragma unroll
                for (int nt = 0; nt < 8; ++nt) {
                    int n = n0 + nt * 8 + g;
                    uint32_t bh[2], bl[2];
                    split_tf32(sm[M1_SB + (kk + tg) * M1_LDB + n],     bh[0], bl[0]);
                    split_tf32(sm[M1_SB + (kk + tg + 4) * M1_LDB + n], bh[1], bl[1]);
                    mma8(acc[mt][nt], ah, bh);
                    mma8(acc[mt][nt], al, bh);
                    mma8(acc[mt][nt], ah, bl);
                }
            }
        }
    }
    __syncthreads();

    #pragma unroll
    for (int mt = 0; mt < 2; ++mt)                      // stage h1+b1 [64][260]
        #pragma unroll
        for (int nt = 0; nt < 8; ++nt) {
            int r = m0 + mt * 16 + g, c = n0 + nt * 8 + tg * 2;
            float bi0 = __ldg(&b1[c]), bi1 = __ldg(&b1[c + 1]);
            sm[r * M1_LDH + c]           = acc[mt][nt][0] + bi0;
            sm[r * M1_LDH + c + 1]       = acc[mt][nt][1] + bi1;
            sm[(r + 8) * M1_LDH + c]     = acc[mt][nt][2] + bi0;
            sm[(r + 8) * M1_LDH + c + 1] = acc[mt][nt][3] + bi1;
        }
    __syncthreads();

    // LayerNorm + ReLU: 4 threads per row, 64 cols each
    int row = tid >> 2, part = tid & 3;
    int node = node0 + row;
    float s = 0.f, ss = 0.f;
    #pragma unroll
    for (int jj = 0; jj < 16; ++jj) {
        int c = (part + 4 * jj) * 4;
        float4 v = *(float4*)&sm[row * M1_LDH + c];
        s  += v.x + v.y + v.z + v.w;
        ss += v.x * v.x + v.y * v.y + v.z * v.z + v.w * v.w;
    }
    s  += __shfl_xor_sync(0xffffffffu, s, 1);
    s  += __shfl_xor_sync(0xffffffffu, s, 2);
    ss += __shfl_xor_sync(0xffffffffu, ss, 1);
    ss += __shfl_xor_sync(0xffffffffu, ss, 2);
    float mean = s * (1.f / 256.f);
    float var  = ss * (1.f / 256.f) - mean * mean;
    float rstd = rsqrtf(var + 1e-5f);
    if (node < NNODES) {
        float* op = g_h1 + (size_t)node * C2;
        #pragma unroll
        for (int jj = 0; jj < 16; ++jj) {
            int c = (part + 4 * jj) * 4;
            float4 v  = *(float4*)&sm[row * M1_LDH + c];
            float4 ga = __ldg((const float4*)&gamma[c]);
            float4 bt = __ldg((const float4*)&beta[c]);
            float4 o;
            o.x = fmaxf((v.x - mean) * rstd * ga.x + bt.x, 0.f);
            o.y = fmaxf((v.y - mean) * rstd * ga.y + bt.y, 0.f);
            o.z = fmaxf((v.z - mean) * rstd * ga.z + bt.z, 0.f);
            o.w = fmaxf((v.w - mean) * rstd * ga.w + bt.w, 0.f);
            *(float4*)&op[c] = o;
        }
    }
}

// ---- kernel 3: out = g_h1 @ W2 + b2 ----
#define M2_LDA 264
#define M2_LDB 136
#define M2_SB  16896
#define M2_NF  21248

__global__ __launch_bounds__(256) void k_mlp2(
    const float* __restrict__ W2, const float* __restrict__ b2,
    float* __restrict__ out)
{
    extern __shared__ float sm[];
    const int tid = threadIdx.x;
    const int node0 = blockIdx.x * 64;
    const int lane = tid & 31, wid = tid >> 5;
    const int g = lane >> 2, tg = lane & 3;
    const int m0 = (wid >> 2) * 32, n0 = (wid & 3) * 32;

    #pragma unroll
    for (int it = 0; it < 16; ++it) {                   // A: h1 tile [64][256]
        int f = tid + it * 256;
        int r = f >> 6, k4 = (f & 63) << 2;
        float4 v = make_float4(0.f, 0.f, 0.f, 0.f);
        if (node0 + r < NNODES) v = *(const float4*)&g_h1[(size_t)(node0 + r) * C2 + k4];
        *(float4*)&sm[r * M2_LDA + k4] = v;
    }

    float acc[2][4][4];
    #pragma unroll
    for (int i = 0; i < 2; ++i)
        #pragma unroll
        for (int j = 0; j < 4; ++j)
            #pragma unroll
            for (int r = 0; r < 4; ++r) acc[i][j][r] = 0.f;

    for (int kc = 0; kc < 8; ++kc) {
        __syncthreads();
        #pragma unroll
        for (int it = 0; it < 4; ++it) {                // B chunk: W2[32][128]
            int f = tid + it * 256;
            int k = f >> 5, n4 = (f & 31) << 2;
            *(float4*)&sm[M2_SB + k * M2_LDB + n4] =
                *(const float4*)&W2[(kc * 32 + k) * CIN + n4];
        }
        __syncthreads();
        #pragma unroll
        for (int kk = 0; kk < 32; kk += 8) {
            int ka = kc * 32 + kk;
            uint32_t bh[4][2], bl[4][2];
            #pragma unroll
            for (int nt = 0; nt < 4; ++nt) {
                int n = n0 + nt * 8 + g;
                split_tf32(sm[M2_SB + (kk + tg) * M2_LDB + n],     bh[nt][0], bl[nt][0]);
                split_tf32(sm[M2_SB + (kk + tg + 4) * M2_LDB + n], bh[nt][1], bl[nt][1]);
            }
            #pragma unroll
            for (int mt = 0; mt < 2; ++mt) {
                int mr = m0 + mt * 16;
                uint32_t ah[4], al[4];
                split_tf32(sm[(mr + g) * M2_LDA + ka + tg],         ah[0], al[0]);
                split_tf32(sm[(mr + g + 8) * M2_LDA + ka + tg],     ah[1], al[1]);
                split_tf32(sm[(mr + g) * M2_LDA + ka + tg + 4],     ah[2], al[2]);
                split_tf32(sm[(mr + g + 8) * M2_LDA + ka + tg + 4], ah[3], al[3]);
                #pragma unroll
                for (int nt = 0; nt < 4; ++nt) {
                    mma8(acc[mt][nt], ah, bh[nt]);
                    mma8(acc[mt][nt], al, bh[nt]);
                    mma8(acc[mt][nt], ah, bl[nt]);
                }
            }
        }
    }

    #pragma unroll
    for (int mt = 0; mt < 2; ++mt)
        #pragma unroll
        for (int nt = 0; nt < 4; ++nt) {
            int r = node0 + m0 + mt * 16 + g;
            int c = n0 + nt * 8 + tg * 2;
            float bi0 = __ldg(&b2[c]), bi1 = __ldg(&b2[c + 1]);
            if (r < NNODES) {
                out[r * CIN + c]     = acc[mt][nt][0] + bi0;
                out[r * CIN + c + 1] = acc[mt][nt][1] + bi1;
            }
            if (r + 8 < NNODES) {
                out[(r + 8) * CIN + c]     = acc[mt][nt][2] + bi0;
                out[(r + 8) * CIN + c + 1] = acc[mt][nt][3] + bi1;
            }
        }
}

extern "C" void kernel_launch(void* const* d_in, const int* in_sizes, int n_in,
                              void* d_out, int out_size) {
    const float* x     = (const float*)d_in[0];
    const int*   ei    = (const int*)d_in[1];
    const float* ea    = (const float*)d_in[2];
    const float* We    = (const float*)d_in[3];
    const float* be    = (const float*)d_in[4];
    const float* W1    = (const float*)d_in[5];
    const float* b1    = (const float*)d_in[6];
    const float* gamma = (const float*)d_in[7];
    const float* beta  = (const float*)d_in[8];
    const float* W2    = (const float*)d_in[9];
    const float* b2    = (const float*)d_in[10];
    const float* eps   = (const float*)d_in[11];
    float* out = (float*)d_out;

    cudaFuncSetAttribute(k_edge, cudaFuncAttributeMaxDynamicSharedMemorySize, E_NF * 4);
    cudaFuncSetAttribute(k_mlp1, cudaFuncAttributeMaxDynamicSharedMemorySize, M1_NF * 4);
    cudaFuncSetAttribute(k_mlp2, cudaFuncAttributeMaxDynamicSharedMemorySize, M2_NF * 4);

    k_init<<<(NNODES * CIN / 4 + 255) / 256, 256>>>(x, eps);
    k_edge<<<NEDGES / 128, 256, E_NF * 4>>>(x, ei, ea, We, be);
    k_mlp1<<<(NNODES + 63) / 64, 256, M1_NF * 4>>>(W1, b1, gamma, beta);
    k_mlp2<<<(NNODES + 63) / 64, 256, M2_NF * 4>>>(W2, b2, out);
}

// round 3
// speedup vs baseline: 1.3848x; 1.3848x over previous
#include <cuda_runtime.h>
#include <cstdint>

#define NNODES 100000
#define NEDGES 640000
#define CIN    128
#define C2     256

__device__ float g_h[NNODES * CIN];            // (1+eps)*x + scatter-add
__device__ float g_h1[(size_t)NNODES * C2];    // post-LN/ReLU hidden

// ---- tf32 helpers (single-pass tf32) ----
__device__ __forceinline__ uint32_t cvt_tf32(float v) {
    uint32_t r; asm("cvt.rna.tf32.f32 %0, %1;" : "=r"(r) : "f"(v)); return r;
}
__device__ __forceinline__ void mma8(float* d, const uint32_t* a, const uint32_t* b) {
    asm volatile(
        "mma.sync.aligned.m16n8k8.row.col.f32.tf32.tf32.f32 "
        "{%0,%1,%2,%3}, {%4,%5,%6,%7}, {%8,%9}, {%0,%1,%2,%3};\n"
        : "+f"(d[0]), "+f"(d[1]), "+f"(d[2]), "+f"(d[3])
        : "r"(a[0]), "r"(a[1]), "r"(a[2]), "r"(a[3]), "r"(b[0]), "r"(b[1]));
}
__device__ __forceinline__ void red_add_v4(float* p, float a, float b, float c, float d) {
    asm volatile("red.global.add.v4.f32 [%0], {%1,%2,%3,%4};"
                 :: "l"(p), "f"(a), "f"(b), "f"(c), "f"(d) : "memory");
}

// ---- kernel 0: h = (1+eps)*x ----
__global__ __launch_bounds__(256) void k_init(const float* __restrict__ x,
                                              const float* __restrict__ eps) {
    int i = blockIdx.x * 256 + threadIdx.x;
    const int total = NNODES * CIN / 4;
    if (i < total) {
        float s = 1.0f + eps[0];
        float4 v = ((const float4*)x)[i];
        v.x *= s; v.y *= s; v.z *= s; v.w *= s;
        ((float4*)g_h)[i] = v;
    }
}

// ---- kernel 1: msg = relu(x[src] + ea@We + be); scatter-add into g_h[dst] ----
#define E_LDA 68
#define E_LDB 132
#define E_LDM 132
#define E_SB  8704
#define E_SBE 17152
#define E_SIDX 17280
#define E_NF  17536

__global__ __launch_bounds__(256) void k_edge(
    const float* __restrict__ x, const int* __restrict__ ei,
    const float* __restrict__ ea, const float* __restrict__ We,
    const float* __restrict__ be)
{
    extern __shared__ float sm[];
    const int tid = threadIdx.x;
    const int e0 = blockIdx.x * 128;

    #pragma unroll
    for (int it = 0; it < 8; ++it) {                    // A: ea tile [128][64]
        int f = tid + it * 256;
        int e = f >> 4, k4 = (f & 15) << 2;
        *(float4*)&sm[e * E_LDA + k4] = *(const float4*)&ea[(e0 + e) * 64 + k4];
    }
    #pragma unroll
    for (int it = 0; it < 8; ++it) {                    // B: We [64][128]
        int f = tid + it * 256;
        int k = f >> 5, n4 = (f & 31) << 2;
        *(float4*)&sm[E_SB + k * E_LDB + n4] = *(const float4*)&We[k * 128 + n4];
    }
    int* sIdx = (int*)&sm[E_SIDX];
    if (tid < 128) {
        sm[E_SBE + tid] = be[tid];
        sIdx[tid]       = ei[e0 + tid];                 // dst
        sIdx[128 + tid] = ei[NEDGES + e0 + tid];        // src
    }
    __syncthreads();

    const int lane = tid & 31, wid = tid >> 5;
    const int g = lane >> 2, tg = lane & 3;
    const int m0 = (wid >> 2) * 64, n0 = (wid & 3) * 32;

    float acc[4][4][4];
    #pragma unroll
    for (int i = 0; i < 4; ++i)
        #pragma unroll
        for (int j = 0; j < 4; ++j)
            #pragma unroll
            for (int r = 0; r < 4; ++r) acc[i][j][r] = 0.f;

    #pragma unroll
    for (int k0 = 0; k0 < 64; k0 += 8) {
        uint32_t bh[4][2];
        #pragma unroll
        for (int nt = 0; nt < 4; ++nt) {
            int n = n0 + nt * 8 + g;
            bh[nt][0] = cvt_tf32(sm[E_SB + (k0 + tg) * E_LDB + n]);
            bh[nt][1] = cvt_tf32(sm[E_SB + (k0 + tg + 4) * E_LDB + n]);
        }
        #pragma unroll
        for (int mt = 0; mt < 4; ++mt) {
            int mr = m0 + mt * 16;
            uint32_t ah[4];
            ah[0] = cvt_tf32(sm[(mr + g) * E_LDA + k0 + tg]);
            ah[1] = cvt_tf32(sm[(mr + g + 8) * E_LDA + k0 + tg]);
            ah[2] = cvt_tf32(sm[(mr + g) * E_LDA + k0 + tg + 4]);
            ah[3] = cvt_tf32(sm[(mr + g + 8) * E_LDA + k0 + tg + 4]);
            #pragma unroll
            for (int nt = 0; nt < 4; ++nt)
                mma8(acc[mt][nt], ah, bh[nt]);
        }
    }
    __syncthreads();                                    // done reading A/B

    #pragma unroll
    for (int mt = 0; mt < 4; ++mt)
        #pragma unroll
        for (int nt = 0; nt < 4; ++nt) {                // stage msg [128][132]
            int r = m0 + mt * 16 + g, c = n0 + nt * 8 + tg * 2;
            sm[r * E_LDM + c]           = acc[mt][nt][0];
            sm[r * E_LDM + c + 1]       = acc[mt][nt][1];
            sm[(r + 8) * E_LDM + c]     = acc[mt][nt][2];
            sm[(r + 8) * E_LDM + c + 1] = acc[mt][nt][3];
        }
    __syncthreads();

    #pragma unroll
    for (int p = 0; p < 4; ++p) {                       // gather+relu+scatter
        int r  = p * 32 + (tid >> 3);
        int c0 = (tid & 7) * 16;
        int dst = sIdx[r], src = sIdx[128 + r];
        const float* xp = x + src * CIN;
        float* hp = g_h + dst * CIN;
        #pragma unroll
        for (int q = 0; q < 4; ++q) {
            int c = c0 + q * 4;
            float4 mv = *(float4*)&sm[r * E_LDM + c];
            float4 xv = *(const float4*)&xp[c];
            float4 bv = *(const float4*)&sm[E_SBE + c];
            red_add_v4(hp + c,
                       fmaxf(mv.x + xv.x + bv.x, 0.f),
                       fmaxf(mv.y + xv.y + bv.y, 0.f),
                       fmaxf(mv.z + xv.z + bv.z, 0.f),
                       fmaxf(mv.w + xv.w + bv.w, 0.f));
        }
    }
}

// ---- kernel 2: g_h1 = relu(LN(h@W1 + b1)) ----
#define M1_LDA 136
#define M1_LDB 264
#define M1_LDH 260
#define M1_SB  8704
#define M1_NF  17152

__global__ __launch_bounds__(256) void k_mlp1(
    const float* __restrict__ W1, const float* __restrict__ b1,
    const float* __restrict__ gamma, const float* __restrict__ beta)
{
    extern __shared__ float sm[];
    const int tid = threadIdx.x;
    const int node0 = blockIdx.x * 64;
    const int lane = tid & 31, wid = tid >> 5;
    const int g = lane >> 2, tg = lane & 3;
    const int m0 = (wid >> 2) * 32, n0 = (wid & 3) * 64;

    #pragma unroll
    for (int it = 0; it < 8; ++it) {                    // A: h tile [64][128]
        int f = tid + it * 256;
        int r = f >> 5, k4 = (f & 31) << 2;
        float4 v = make_float4(0.f, 0.f, 0.f, 0.f);
        if (node0 + r < NNODES) v = *(const float4*)&g_h[(node0 + r) * CIN + k4];
        *(float4*)&sm[r * M1_LDA + k4] = v;
    }

    float acc[2][8][4];
    #pragma unroll
    for (int i = 0; i < 2; ++i)
        #pragma unroll
        for (int j = 0; j < 8; ++j)
            #pragma unroll
            for (int r = 0; r < 4; ++r) acc[i][j][r] = 0.f;

    for (int kc = 0; kc < 4; ++kc) {
        __syncthreads();
        #pragma unroll
        for (int it = 0; it < 8; ++it) {                // B chunk: W1[32][256]
            int f = tid + it * 256;
            int k = f >> 6, n4 = (f & 63) << 2;
            *(float4*)&sm[M1_SB + k * M1_LDB + n4] =
                *(const float4*)&W1[(kc * 32 + k) * C2 + n4];
        }
        __syncthreads();
        #pragma unroll
        for (int kk = 0; kk < 32; kk += 8) {
            int ka = kc * 32 + kk;
            #pragma unroll
            for (int mt = 0; mt < 2; ++mt) {
                int mr = m0 + mt * 16;
                uint32_t ah[4];
                ah[0] = cvt_tf32(sm[(mr + g) * M1_LDA + ka + tg]);
                ah[1] = cvt_tf32(sm[(mr + g + 8) * M1_LDA + ka + tg]);
                ah[2] = cvt_tf32(sm[(mr + g) * M1_LDA + ka + tg + 4]);
                ah[3] = cvt_tf32(sm[(mr + g + 8) * M1_LDA + ka + tg + 4]);
                #pragma unroll
                for (int nt = 0; nt < 8; ++nt) {
                    int n = n0 + nt * 8 + g;
                    uint32_t bh[2];
                    bh[0] = cvt_tf32(sm[M1_SB + (kk + tg) * M1_LDB + n]);
                    bh[1] = cvt_tf32(sm[M1_SB + (kk + tg + 4) * M1_LDB + n]);
                    mma8(acc[mt][nt], ah, bh);
                }
            }
        }
    }
    __syncthreads();

    #pragma unroll
    for (int mt = 0; mt < 2; ++mt)                      // stage h1+b1 [64][260]
        #pragma unroll
        for (int nt = 0; nt < 8; ++nt) {
            int r = m0 + mt * 16 + g, c = n0 + nt * 8 + tg * 2;
            float bi0 = __ldg(&b1[c]), bi1 = __ldg(&b1[c + 1]);
            sm[r * M1_LDH + c]           = acc[mt][nt][0] + bi0;
            sm[r * M1_LDH + c + 1]       = acc[mt][nt][1] + bi1;
            sm[(r + 8) * M1_LDH + c]     = acc[mt][nt][2] + bi0;
            sm[(r + 8) * M1_LDH + c + 1] = acc[mt][nt][3] + bi1;
        }
    __syncthreads();

    // LayerNorm + ReLU: 4 threads per row, 64 cols each
    int row = tid >> 2, part = tid & 3;
    int node = node0 + row;
    float s = 0.f, ss = 0.f;
    #pragma unroll
    for (int jj = 0; jj < 16; ++jj) {
        int c = (part + 4 * jj) * 4;
        float4 v = *(float4*)&sm[row * M1_LDH + c];
        s  += v.x + v.y + v.z + v.w;
        ss += v.x * v.x + v.y * v.y + v.z * v.z + v.w * v.w;
    }
    s  += __shfl_xor_sync(0xffffffffu, s, 1);
    s  += __shfl_xor_sync(0xffffffffu, s, 2);
    ss += __shfl_xor_sync(0xffffffffu, ss, 1);
    ss += __shfl_xor_sync(0xffffffffu, ss, 2);
    float mean = s * (1.f / 256.f);
    float var  = ss * (1.f / 256.f) - mean * mean;
    float rstd = rsqrtf(var + 1e-5f);
    if (node < NNODES) {
        float* op = g_h1 + (size_t)node * C2;
        #pragma unroll
        for (int jj = 0; jj < 16; ++jj) {
            int c = (part + 4 * jj) * 4;
            float4 v  = *(float4*)&sm[row * M1_LDH + c];
            float4 ga = __ldg((const float4*)&gamma[c]);
            float4 bt = __ldg((const float4*)&beta[c]);
            float4 o;
            o.x = fmaxf((v.x - mean) * rstd * ga.x + bt.x, 0.f);
            o.y = fmaxf((v.y - mean) * rstd * ga.y + bt.y, 0.f);
            o.z = fmaxf((v.z - mean) * rstd * ga.z + bt.z, 0.f);
            o.w = fmaxf((v.w - mean) * rstd * ga.w + bt.w, 0.f);
            *(float4*)&op[c] = o;
        }
    }
}

// ---- kernel 3: out = g_h1 @ W2 + b2 ----
#define M2_LDA 264
#define M2_LDB 136
#define M2_SB  16896
#define M2_NF  21248

__global__ __launch_bounds__(256) void k_mlp2(
    const float* __restrict__ W2, const float* __restrict__ b2,
    float* __restrict__ out)
{
    extern __shared__ float sm[];
    const int tid = threadIdx.x;
    const int node0 = blockIdx.x * 64;
    const int lane = tid & 31, wid = tid >> 5;
    const int g = lane >> 2, tg = lane & 3;
    const int m0 = (wid >> 2) * 32, n0 = (wid & 3) * 32;

    #pragma unroll
    for (int it = 0; it < 16; ++it) {                   // A: h1 tile [64][256]
        int f = tid + it * 256;
        int r = f >> 6, k4 = (f & 63) << 2;
        float4 v = make_float4(0.f, 0.f, 0.f, 0.f);
        if (node0 + r < NNODES) v = *(const float4*)&g_h1[(size_t)(node0 + r) * C2 + k4];
        *(float4*)&sm[r * M2_LDA + k4] = v;
    }

    float acc[2][4][4];
    #pragma unroll
    for (int i = 0; i < 2; ++i)
        #pragma unroll
        for (int j = 0; j < 4; ++j)
            #pragma unroll
            for (int r = 0; r < 4; ++r) acc[i][j][r] = 0.f;

    for (int kc = 0; kc < 8; ++kc) {
        __syncthreads();
        #pragma unroll
        for (int it = 0; it < 4; ++it) {                // B chunk: W2[32][128]
            int f = tid + it * 256;
            int k = f >> 5, n4 = (f & 31) << 2;
            *(float4*)&sm[M2_SB + k * M2_LDB + n4] =
                *(const float4*)&W2[(kc * 32 + k) * CIN + n4];
        }
        __syncthreads();
        #pragma unroll
        for (int kk = 0; kk < 32; kk += 8) {
            int ka = kc * 32 + kk;
            uint32_t bh[4][2];
            #pragma unroll
            for (int nt = 0; nt < 4; ++nt) {
                int n = n0 + nt * 8 + g;
                bh[nt][0] = cvt_tf32(sm[M2_SB + (kk + tg) * M2_LDB + n]);
                bh[nt][1] = cvt_tf32(sm[M2_SB + (kk + tg + 4) * M2_LDB + n]);
            }
            #pragma unroll
            for (int mt = 0; mt < 2; ++mt) {
                int mr = m0 + mt * 16;
                uint32_t ah[4];
                ah[0] = cvt_tf32(sm[(mr + g) * M2_LDA + ka + tg]);
                ah[1] = cvt_tf32(sm[(mr + g + 8) * M2_LDA + ka + tg]);
                ah[2] = cvt_tf32(sm[(mr + g) * M2_LDA + ka + tg + 4]);
                ah[3] = cvt_tf32(sm[(mr + g + 8) * M2_LDA + ka + tg + 4]);
                #pragma unroll
                for (int nt = 0; nt < 4; ++nt)
                    mma8(acc[mt][nt], ah, bh[nt]);
            }
        }
    }

    #pragma unroll
    for (int mt = 0; mt < 2; ++mt)
        #pragma unroll
        for (int nt = 0; nt < 4; ++nt) {
            int r = node0 + m0 + mt * 16 + g;
            int c = n0 + nt * 8 + tg * 2;
            float bi0 = __ldg(&b2[c]), bi1 = __ldg(&b2[c + 1]);
            if (r < NNODES) {
                out[r * CIN + c]     = acc[mt][nt][0] + bi0;
                out[r * CIN + c + 1] = acc[mt][nt][1] + bi1;
            }
            if (r + 8 < NNODES) {
                out[(r + 8) * CIN + c]     = acc[mt][nt][2] + bi0;
                out[(r + 8) * CIN + c + 1] = acc[mt][nt][3] + bi1;
            }
        }
}

extern "C" void kernel_launch(void* const* d_in, const int* in_sizes, int n_in,
                              void* d_out, int out_size) {
    const float* x     = (const float*)d_in[0];
    const int*   ei    = (const int*)d_in[1];
    const float* ea    = (const float*)d_in[2];
    const float* We    = (const float*)d_in[3];
    const float* be    = (const float*)d_in[4];
    const float* W1    = (const float*)d_in[5];
    const float* b1    = (const float*)d_in[6];
    const float* gamma = (const float*)d_in[7];
    const float* beta  = (const float*)d_in[8];
    const float* W2    = (const float*)d_in[9];
    const float* b2    = (const float*)d_in[10];
    const float* eps   = (const float*)d_in[11];
    float* out = (float*)d_out;

    cudaFuncSetAttribute(k_edge, cudaFuncAttributeMaxDynamicSharedMemorySize, E_NF * 4);
    cudaFuncSetAttribute(k_mlp1, cudaFuncAttributeMaxDynamicSharedMemorySize, M1_NF * 4);
    cudaFuncSetAttribute(k_mlp2, cudaFuncAttributeMaxDynamicSharedMemorySize, M2_NF * 4);

    k_init<<<(NNODES * CIN / 4 + 255) / 256, 256>>>(x, eps);
    k_edge<<<NEDGES / 128, 256, E_NF * 4>>>(x, ei, ea, We, be);
    k_mlp1<<<(NNODES + 63) / 64, 256, M1_NF * 4>>>(W1, b1, gamma, beta);
    k_mlp2<<<(NNODES + 63) / 64, 256, M2_NF * 4>>>(W2, b2, out);
}

// round 4
// speedup vs baseline: 1.4059x; 1.0153x over previous
#include <cuda_runtime.h>
#include <cstdint>

#define NNODES 100000
#define NEDGES 640000
#define CIN    128
#define C2     256

__device__ float g_h[NNODES * CIN];            // (1+eps)*x + scatter-add
__device__ float g_h1[(size_t)NNODES * C2];    // post-LN/ReLU hidden

// ---- helpers ----
__device__ __forceinline__ uint32_t cvt_tf32(float v) {
    uint32_t r; asm("cvt.rna.tf32.f32 %0, %1;" : "=r"(r) : "f"(v)); return r;
}
__device__ __forceinline__ void mma8(float* d, const uint32_t* a, const uint32_t* b) {
    asm volatile(
        "mma.sync.aligned.m16n8k8.row.col.f32.tf32.tf32.f32 "
        "{%0,%1,%2,%3}, {%4,%5,%6,%7}, {%8,%9}, {%0,%1,%2,%3};\n"
        : "+f"(d[0]), "+f"(d[1]), "+f"(d[2]), "+f"(d[3])
        : "r"(a[0]), "r"(a[1]), "r"(a[2]), "r"(a[3]), "r"(b[0]), "r"(b[1]));
}
__device__ __forceinline__ void ldsm4(uint32_t addr, uint32_t* r) {
    asm volatile("ldmatrix.sync.aligned.m8n8.x4.shared.b16 {%0,%1,%2,%3}, [%4];"
                 : "=r"(r[0]), "=r"(r[1]), "=r"(r[2]), "=r"(r[3]) : "r"(addr));
}
__device__ __forceinline__ void red_add_v4(float* p, float a, float b, float c, float d) {
    asm volatile("red.global.add.v4.f32 [%0], {%1,%2,%3,%4};"
                 :: "l"(p), "f"(a), "f"(b), "f"(c), "f"(d) : "memory");
}
__device__ __forceinline__ uint32_t smem_u32(const void* p) {
    return (uint32_t)__cvta_generic_to_shared(p);
}

// ---- kernel 0: h = (1+eps)*x ----
__global__ __launch_bounds__(256) void k_init(const float* __restrict__ x,
                                              const float* __restrict__ eps) {
    int i = blockIdx.x * 256 + threadIdx.x;
    const int total = NNODES * CIN / 4;
    if (i < total) {
        float s = 1.0f + eps[0];
        float4 v = ((const float4*)x)[i];
        v.x *= s; v.y *= s; v.z *= s; v.w *= s;
        ((float4*)g_h)[i] = v;
    }
}

// ============ kernel 1: msg = relu(x[src] + ea@We + be); scatter into g_h ============
// A: ea tile [128 rows][64 k] swizzled tf32.  B: We transposed [128 n][64 k] swizzled.
#define E_LDA  64
#define E_LDBT 64
#define E_SB   8192
#define E_LDM  132
#define E_SBE  16896
#define E_SIDX 17024
#define E_NF   17280

__global__ __launch_bounds__(256) void k_edge(
    const float* __restrict__ x, const int* __restrict__ ei,
    const float* __restrict__ ea, const float* __restrict__ We,
    const float* __restrict__ be)
{
    extern __shared__ float sm[];
    const int tid = threadIdx.x;
    const int e0 = blockIdx.x * 128;

    #pragma unroll
    for (int it = 0; it < 8; ++it) {                    // A: ea [128][64], round+swizzle
        int f = tid + it * 256;
        int e = f >> 4, kg = f & 15;
        float4 v = *(const float4*)&ea[(e0 + e) * 64 + kg * 4];
        int c = kg ^ (e & 7);
        uint32_t* d = (uint32_t*)&sm[e * E_LDA + c * 4];
        d[0] = cvt_tf32(v.x); d[1] = cvt_tf32(v.y);
        d[2] = cvt_tf32(v.z); d[3] = cvt_tf32(v.w);
    }
    #pragma unroll
    for (int it = 0; it < 8; ++it) {                    // B: We^T [128 n][64 k]
        int f = tid + it * 256;
        int n = f & 127, kg = f >> 7;                   // kg 0..15
        int k4 = kg * 4;
        uint32_t r0 = cvt_tf32(We[(k4 + 0) * 128 + n]);
        uint32_t r1 = cvt_tf32(We[(k4 + 1) * 128 + n]);
        uint32_t r2 = cvt_tf32(We[(k4 + 2) * 128 + n]);
        uint32_t r3 = cvt_tf32(We[(k4 + 3) * 128 + n]);
        int c = kg ^ (n & 7);
        uint32_t* d = (uint32_t*)&sm[E_SB + n * E_LDBT + c * 4];
        d[0] = r0; d[1] = r1; d[2] = r2; d[3] = r3;
    }
    int* sIdx = (int*)&sm[E_SIDX];
    if (tid < 128) {
        sm[E_SBE + tid] = be[tid];
        sIdx[tid]       = ei[e0 + tid];                 // dst
        sIdx[128 + tid] = ei[NEDGES + e0 + tid];        // src
    }
    __syncthreads();

    const int lane = tid & 31, wid = tid >> 5;
    const int g = lane >> 2, tg = lane & 3;
    const int m0 = (wid >> 2) * 64, n0 = (wid & 3) * 32;
    const int lr = lane & 7, lm = lane >> 3;
    const uint32_t smA = smem_u32(sm);
    const uint32_t smB = smA + E_SB * 4;
    const int aK = lm >> 1, bK = lm & 1;

    uint32_t aBase[4], bBase[2];
    #pragma unroll
    for (int mt = 0; mt < 4; ++mt)
        aBase[mt] = smA + (m0 + mt * 16 + lr + (lm & 1) * 8) * E_LDA * 4;
    #pragma unroll
    for (int np = 0; np < 2; ++np)
        bBase[np] = smB + (n0 + np * 16 + lr + (lm >> 1) * 8) * E_LDBT * 4;

    float acc[4][4][4];
    #pragma unroll
    for (int i = 0; i < 4; ++i)
        #pragma unroll
        for (int j = 0; j < 4; ++j)
            #pragma unroll
            for (int r = 0; r < 4; ++r) acc[i][j][r] = 0.f;

    #pragma unroll
    for (int k0 = 0; k0 < 64; k0 += 8) {
        int k2 = k0 >> 2;
        uint32_t bh[4][2];
        {
            uint32_t t[4];
            uint32_t boff = (uint32_t)(((k2 + bK) ^ lr) << 4);
            ldsm4(bBase[0] + boff, t);
            bh[0][0] = t[0]; bh[0][1] = t[1]; bh[1][0] = t[2]; bh[1][1] = t[3];
            ldsm4(bBase[1] + boff, t);
            bh[2][0] = t[0]; bh[2][1] = t[1]; bh[3][0] = t[2]; bh[3][1] = t[3];
        }
        uint32_t aoff = (uint32_t)(((k2 + aK) ^ lr) << 4);
        #pragma unroll
        for (int mt = 0; mt < 4; ++mt) {
            uint32_t ah[4];
            ldsm4(aBase[mt] + aoff, ah);
            #pragma unroll
            for (int nt = 0; nt < 4; ++nt)
                mma8(acc[mt][nt], ah, bh[nt]);
        }
    }
    __syncthreads();                                    // done reading A/B

    #pragma unroll
    for (int mt = 0; mt < 4; ++mt)
        #pragma unroll
        for (int nt = 0; nt < 4; ++nt) {                // stage msg [128][132]
            int r = m0 + mt * 16 + g, c = n0 + nt * 8 + tg * 2;
            sm[r * E_LDM + c]           = acc[mt][nt][0];
            sm[r * E_LDM + c + 1]       = acc[mt][nt][1];
            sm[(r + 8) * E_LDM + c]     = acc[mt][nt][2];
            sm[(r + 8) * E_LDM + c + 1] = acc[mt][nt][3];
        }
    __syncthreads();

    #pragma unroll
    for (int p = 0; p < 4; ++p) {                       // gather+relu+scatter
        int r  = p * 32 + (tid >> 3);
        int c0 = (tid & 7) * 16;
        int dst = sIdx[r], src = sIdx[128 + r];
        const float* xp = x + src * CIN;
        float* hp = g_h + dst * CIN;
        #pragma unroll
        for (int q = 0; q < 4; ++q) {
            int c = c0 + q * 4;
            float4 mv = *(float4*)&sm[r * E_LDM + c];
            float4 xv = *(const float4*)&xp[c];
            float4 bv = *(const float4*)&sm[E_SBE + c];
            red_add_v4(hp + c,
                       fmaxf(mv.x + xv.x + bv.x, 0.f),
                       fmaxf(mv.y + xv.y + bv.y, 0.f),
                       fmaxf(mv.z + xv.z + bv.z, 0.f),
                       fmaxf(mv.w + xv.w + bv.w, 0.f));
        }
    }
}

// ============ kernel 2: g_h1 = relu(LN(h@W1 + b1)) ============
// A: h tile [64][128] swizzled. B: W1 chunk transposed [256 n][32 k] swizzled.
#define M1_LDA  128
#define M1_LDBT 32
#define M1_SB   8192
#define M1_LDH  260
#define M1_NF   16640

__global__ __launch_bounds__(256) void k_mlp1(
    const float* __restrict__ W1, const float* __restrict__ b1,
    const float* __restrict__ gamma, const float* __restrict__ beta)
{
    extern __shared__ float sm[];
    const int tid = threadIdx.x;
    const int node0 = blockIdx.x * 64;
    const int lane = tid & 31, wid = tid >> 5;
    const int g = lane >> 2, tg = lane & 3;
    const int m0 = (wid >> 2) * 32, n0 = (wid & 3) * 64;
    const int lr = lane & 7, lm = lane >> 3;
    const int aK = lm >> 1, bK = lm & 1;

    #pragma unroll
    for (int it = 0; it < 8; ++it) {                    // A: h [64][128]
        int f = tid + it * 256;
        int r = f >> 5, kg = f & 31;
        float4 v = make_float4(0.f, 0.f, 0.f, 0.f);
        if (node0 + r < NNODES) v = *(const float4*)&g_h[(node0 + r) * CIN + kg * 4];
        int c = kg ^ (r & 7);
        uint32_t* d = (uint32_t*)&sm[r * M1_LDA + c * 4];
        d[0] = cvt_tf32(v.x); d[1] = cvt_tf32(v.y);
        d[2] = cvt_tf32(v.z); d[3] = cvt_tf32(v.w);
    }

    const uint32_t smA = smem_u32(sm);
    const uint32_t smB = smA + M1_SB * 4;
    uint32_t aBase[2], bBase[4];
    #pragma unroll
    for (int mt = 0; mt < 2; ++mt)
        aBase[mt] = smA + (m0 + mt * 16 + lr + (lm & 1) * 8) * M1_LDA * 4;
    #pragma unroll
    for (int np = 0; np < 4; ++np)
        bBase[np] = smB + (n0 + np * 16 + lr + (lm >> 1) * 8) * M1_LDBT * 4;

    float acc[2][8][4];
    #pragma unroll
    for (int i = 0; i < 2; ++i)
        #pragma unroll
        for (int j = 0; j < 8; ++j)
            #pragma unroll
            for (int r = 0; r < 4; ++r) acc[i][j][r] = 0.f;

    for (int kc = 0; kc < 4; ++kc) {
        __syncthreads();
        #pragma unroll
        for (int it = 0; it < 8; ++it) {                // B: W1^T chunk [256][32]
            int f = tid + it * 256;
            int n = f & 255, kg = f >> 8;               // kg 0..7
            int kglob = kc * 32 + kg * 4;
            uint32_t r0 = cvt_tf32(W1[(kglob + 0) * C2 + n]);
            uint32_t r1 = cvt_tf32(W1[(kglob + 1) * C2 + n]);
            uint32_t r2 = cvt_tf32(W1[(kglob + 2) * C2 + n]);
            uint32_t r3 = cvt_tf32(W1[(kglob + 3) * C2 + n]);
            int c = kg ^ (n & 7);
            uint32_t* d = (uint32_t*)&sm[M1_SB + n * M1_LDBT + c * 4];
            d[0] = r0; d[1] = r1; d[2] = r2; d[3] = r3;
        }
        __syncthreads();
        #pragma unroll
        for (int kk = 0; kk < 32; kk += 8) {
            int k2a = (kc * 32 + kk) >> 2;
            int k2b = kk >> 2;
            uint32_t bh[8][2];
            uint32_t boff = (uint32_t)(((k2b + bK) ^ lr) << 4);
            #pragma unroll
            for (int np = 0; np < 4; ++np) {
                uint32_t t[4];
                ldsm4(bBase[np] + boff, t);
                bh[np * 2][0]     = t[0]; bh[np * 2][1]     = t[1];
                bh[np * 2 + 1][0] = t[2]; bh[np * 2 + 1][1] = t[3];
            }
            uint32_t aoff = (uint32_t)(((k2a + aK) ^ lr) << 4);
            #pragma unroll
            for (int mt = 0; mt < 2; ++mt) {
                uint32_t ah[4];
                ldsm4(aBase[mt] + aoff, ah);
                #pragma unroll
                for (int nt = 0; nt < 8; ++nt)
                    mma8(acc[mt][nt], ah, bh[nt]);
            }
        }
    }
    __syncthreads();

    #pragma unroll
    for (int mt = 0; mt < 2; ++mt)                      // stage h1+b1 [64][260]
        #pragma unroll
        for (int nt = 0; nt < 8; ++nt) {
            int r = m0 + mt * 16 + g, c = n0 + nt * 8 + tg * 2;
            float bi0 = __ldg(&b1[c]), bi1 = __ldg(&b1[c + 1]);
            sm[r * M1_LDH + c]           = acc[mt][nt][0] + bi0;
            sm[r * M1_LDH + c + 1]       = acc[mt][nt][1] + bi1;
            sm[(r + 8) * M1_LDH + c]     = acc[mt][nt][2] + bi0;
            sm[(r + 8) * M1_LDH + c + 1] = acc[mt][nt][3] + bi1;
        }
    __syncthreads();

    // LayerNorm + ReLU: 4 threads per row
    int row = tid >> 2, part = tid & 3;
    int node = node0 + row;
    float s = 0.f, ss = 0.f;
    #pragma unroll
    for (int jj = 0; jj < 16; ++jj) {
        int c = (part + 4 * jj) * 4;
        float4 v = *(float4*)&sm[row * M1_LDH + c];
        s  += v.x + v.y + v.z + v.w;
        ss += v.x * v.x + v.y * v.y + v.z * v.z + v.w * v.w;
    }
    s  += __shfl_xor_sync(0xffffffffu, s, 1);
    s  += __shfl_xor_sync(0xffffffffu, s, 2);
    ss += __shfl_xor_sync(0xffffffffu, ss, 1);
    ss += __shfl_xor_sync(0xffffffffu, ss, 2);
    float mean = s * (1.f / 256.f);
    float var  = ss * (1.f / 256.f) - mean * mean;
    float rstd = rsqrtf(var + 1e-5f);
    if (node < NNODES) {
        float* op = g_h1 + (size_t)node * C2;
        #pragma unroll
        for (int jj = 0; jj < 16; ++jj) {
            int c = (part + 4 * jj) * 4;
            float4 v  = *(float4*)&sm[row * M1_LDH + c];
            float4 ga = __ldg((const float4*)&gamma[c]);
            float4 bt = __ldg((const float4*)&beta[c]);
            float4 o;
            o.x = fmaxf((v.x - mean) * rstd * ga.x + bt.x, 0.f);
            o.y = fmaxf((v.y - mean) * rstd * ga.y + bt.y, 0.f);
            o.z = fmaxf((v.z - mean) * rstd * ga.z + bt.z, 0.f);
            o.w = fmaxf((v.w - mean) * rstd * ga.w + bt.w, 0.f);
            *(float4*)&op[c] = o;
        }
    }
}

// ============ kernel 3: out = g_h1 @ W2 + b2 ============
// A: h1 tile [64][256] swizzled. B: W2 chunk transposed [128 n][32 k] swizzled.
#define M2_LDA  256
#define M2_LDBT 32
#define M2_SB   16384
#define M2_NF   20480

__global__ __launch_bounds__(256) void k_mlp2(
    const float* __restrict__ W2, const float* __restrict__ b2,
    float* __restrict__ out)
{
    extern __shared__ float sm[];
    const int tid = threadIdx.x;
    const int node0 = blockIdx.x * 64;
    const int lane = tid & 31, wid = tid >> 5;
    const int g = lane >> 2, tg = lane & 3;
    const int m0 = (wid >> 2) * 32, n0 = (wid & 3) * 32;
    const int lr = lane & 7, lm = lane >> 3;
    const int aK = lm >> 1, bK = lm & 1;

    #pragma unroll
    for (int it = 0; it < 16; ++it) {                   // A: h1 [64][256]
        int f = tid + it * 256;
        int r = f >> 6, kg = f & 63;
        float4 v = make_float4(0.f, 0.f, 0.f, 0.f);
        if (node0 + r < NNODES) v = *(const float4*)&g_h1[(size_t)(node0 + r) * C2 + kg * 4];
        int c = kg ^ (r & 7);
        uint32_t* d = (uint32_t*)&sm[r * M2_LDA + c * 4];
        d[0] = cvt_tf32(v.x); d[1] = cvt_tf32(v.y);
        d[2] = cvt_tf32(v.z); d[3] = cvt_tf32(v.w);
    }

    const uint32_t smA = smem_u32(sm);
    const uint32_t smB = smA + M2_SB * 4;
    uint32_t aBase[2], bBase[2];
    #pragma unroll
    for (int mt = 0; mt < 2; ++mt)
        aBase[mt] = smA + (m0 + mt * 16 + lr + (lm & 1) * 8) * M2_LDA * 4;
    #pragma unroll
    for (int np = 0; np < 2; ++np)
        bBase[np] = smB + (n0 + np * 16 + lr + (lm >> 1) * 8) * M2_LDBT * 4;

    float acc[2][4][4];
    #pragma unroll
    for (int i = 0; i < 2; ++i)
        #pragma unroll
        for (int j = 0; j < 4; ++j)
            #pragma unroll
            for (int r = 0; r < 4; ++r) acc[i][j][r] = 0.f;

    for (int kc = 0; kc < 8; ++kc) {
        __syncthreads();
        #pragma unroll
        for (int it = 0; it < 4; ++it) {                // B: W2^T chunk [128][32]
            int f = tid + it * 256;
            int n = f & 127, kg = f >> 7;               // kg 0..7
            int kglob = kc * 32 + kg * 4;
            uint32_t r0 = cvt_tf32(W2[(kglob + 0) * CIN + n]);
            uint32_t r1 = cvt_tf32(W2[(kglob + 1) * CIN + n]);
            uint32_t r2 = cvt_tf32(W2[(kglob + 2) * CIN + n]);
            uint32_t r3 = cvt_tf32(W2[(kglob + 3) * CIN + n]);
            int c = kg ^ (n & 7);
            uint32_t* d = (uint32_t*)&sm[M2_SB + n * M2_LDBT + c * 4];
            d[0] = r0; d[1] = r1; d[2] = r2; d[3] = r3;
        }
        __syncthreads();
        #pragma unroll
        for (int kk = 0; kk < 32; kk += 8) {
            int k2a = (kc * 32 + kk) >> 2;
            int k2b = kk >> 2;
            uint32_t bh[4][2];
            uint32_t boff = (uint32_t)(((k2b + bK) ^ lr) << 4);
            {
                uint32_t t[4];
                ldsm4(bBase[0] + boff, t);
                bh[0][0] = t[0]; bh[0][1] = t[1]; bh[1][0] = t[2]; bh[1][1] = t[3];
                ldsm4(bBase[1] + boff, t);
                bh[2][0] = t[0]; bh[2][1] = t[1]; bh[3][0] = t[2]; bh[3][1] = t[3];
            }
            uint32_t aoff = (uint32_t)(((k2a + aK) ^ lr) << 4);
            #pragma unroll
            for (int mt = 0; mt < 2; ++mt) {
                uint32_t ah[4];
                ldsm4(aBase[mt] + aoff, ah);
                #pragma unroll
                for (int nt = 0; nt < 4; ++nt)
                    mma8(acc[mt][nt], ah, bh[nt]);
            }
        }
    }

    #pragma unroll
    for (int mt = 0; mt < 2; ++mt)
        #pragma unroll
        for (int nt = 0; nt < 4; ++nt) {
            int r = node0 + m0 + mt * 16 + g;
            int c = n0 + nt * 8 + tg * 2;
            float bi0 = __ldg(&b2[c]), bi1 = __ldg(&b2[c + 1]);
            if (r < NNODES) {
                out[r * CIN + c]     = acc[mt][nt][0] + bi0;
                out[r * CIN + c + 1] = acc[mt][nt][1] + bi1;
            }
            if (r + 8 < NNODES) {
                out[(r + 8) * CIN + c]     = acc[mt][nt][2] + bi0;
                out[(r + 8) * CIN + c + 1] = acc[mt][nt][3] + bi1;
            }
        }
}

extern "C" void kernel_launch(void* const* d_in, const int* in_sizes, int n_in,
                              void* d_out, int out_size) {
    const float* x     = (const float*)d_in[0];
    const int*   ei    = (const int*)d_in[1];
    const float* ea    = (const float*)d_in[2];
    const float* We    = (const float*)d_in[3];
    const float* be    = (const float*)d_in[4];
    const float* W1    = (const float*)d_in[5];
    const float* b1    = (const float*)d_in[6];
    const float* gamma = (const float*)d_in[7];
    const float* beta  = (const float*)d_in[8];
    const float* W2    = (const float*)d_in[9];
    const float* b2    = (const float*)d_in[10];
    const float* eps   = (const float*)d_in[11];
    float* out = (float*)d_out;

    cudaFuncSetAttribute(k_edge, cudaFuncAttributeMaxDynamicSharedMemorySize, E_NF * 4);
    cudaFuncSetAttribute(k_mlp1, cudaFuncAttributeMaxDynamicSharedMemorySize, M1_NF * 4);
    cudaFuncSetAttribute(k_mlp2, cudaFuncAttributeMaxDynamicSharedMemorySize, M2_NF * 4);

    k_init<<<(NNODES * CIN / 4 + 255) / 256, 256>>>(x, eps);
    k_edge<<<NEDGES / 128, 256, E_NF * 4>>>(x, ei, ea, We, be);
    k_mlp1<<<(NNODES + 63) / 64, 256, M1_NF * 4>>>(W1, b1, gamma, beta);
    k_mlp2<<<(NNODES + 63) / 64, 256, M2_NF * 4>>>(W2, b2, out);
}